// round 1
// baseline (speedup 1.0000x reference)
#include <cuda_runtime.h>
#include <cstdint>

#define N_ROWS 32768
#define K_CODES 8192
#define D_DIM 512

#define BM 128
#define BN 128
#define BK 16
#define TM 8
#define TN 8
#define NTHREADS 256

// Scratch (no allocations allowed in kernel_launch)
__device__ float  g_znorm[N_ROWS];
__device__ float  g_enorm[K_CODES];
__device__ int    g_idx[N_ROWS];
__device__ double g_rowpart[N_ROWS];

// ---------------------------------------------------------------------------
// Row sums of squares for z (N rows) and e (K rows): one warp per row.
// ---------------------------------------------------------------------------
__global__ void norms_kernel(const float* __restrict__ z,
                             const float* __restrict__ e) {
    int gw   = (blockIdx.x * blockDim.x + threadIdx.x) >> 5;
    int lane = threadIdx.x & 31;
    if (gw >= N_ROWS + K_CODES) return;
    const float* p = (gw < N_ROWS) ? (z + (size_t)gw * D_DIM)
                                   : (e + (size_t)(gw - N_ROWS) * D_DIM);
    float acc = 0.0f;
    #pragma unroll
    for (int i = lane; i < D_DIM; i += 32) {
        float v = p[i];
        acc = fmaf(v, v, acc);
    }
    #pragma unroll
    for (int o = 16; o > 0; o >>= 1)
        acc += __shfl_down_sync(0xffffffffu, acc, o);
    if (lane == 0) {
        if (gw < N_ROWS) g_znorm[gw] = acc;
        else             g_enorm[gw - N_ROWS] = acc;
    }
}

// ---------------------------------------------------------------------------
// Fused GEMM + running argmin. Each block owns BM rows, sweeps all K codes in
// BN-chunks; 8x8 register tile per thread; double-buffered smem tiles.
// Distance replicates ref rounding: fl(fl(znorm+enorm) - 2*dot), first-min
// tie-break (lowest code index wins on equality).
// ---------------------------------------------------------------------------
__global__ __launch_bounds__(NTHREADS, 2)
void argmin_kernel(const float* __restrict__ Z, const float* __restrict__ E) {
    __shared__ float Zs[2][BK][BM];
    __shared__ float Es[2][BK][BN];
    __shared__ float zn_s[BM];
    __shared__ float en_s[BN];

    const int t    = threadIdx.x;
    const int tx   = t & 15;   // 16 column groups
    const int ty   = t >> 4;   // 16 row groups
    const int row0 = blockIdx.x * BM;

    if (t < BM) zn_s[t] = g_znorm[row0 + t];

    float best[TM];
    int   bidx[TM];
    #pragma unroll
    for (int i = 0; i < TM; i++) { best[i] = 3.4028235e38f; bidx[i] = 0x7fffffff; }

    const int NCHUNK = K_CODES / BN;   // 64
    const int NT     = D_DIM / BK;     // 32

    for (int cb = 0; cb < NCHUNK; cb++) {
        const int col0 = cb * BN;
        __syncthreads();               // protect en_s / smem vs previous chunk
        if (t < BN) en_s[t] = g_enorm[col0 + t];

        float acc[TM][TN];
        #pragma unroll
        for (int i = 0; i < TM; i++)
            #pragma unroll
            for (int j = 0; j < TN; j++) acc[i][j] = 0.0f;

        float4 zr[2], er[2];

        // prologue: load tile 0, store into buffer 0, prefetch tile 1
        #pragma unroll
        for (int r = 0; r < 2; r++) {
            int f = t * 2 + r, row = f >> 2, ds = (f & 3) * 4;
            zr[r] = *(const float4*)(Z + (size_t)(row0 + row) * D_DIM + ds);
            er[r] = *(const float4*)(E + (size_t)(col0 + row) * D_DIM + ds);
        }
        #pragma unroll
        for (int r = 0; r < 2; r++) {
            int f = t * 2 + r, row = f >> 2, ds = (f & 3) * 4;
            Zs[0][ds + 0][row] = zr[r].x; Zs[0][ds + 1][row] = zr[r].y;
            Zs[0][ds + 2][row] = zr[r].z; Zs[0][ds + 3][row] = zr[r].w;
            Es[0][ds + 0][row] = er[r].x; Es[0][ds + 1][row] = er[r].y;
            Es[0][ds + 2][row] = er[r].z; Es[0][ds + 3][row] = er[r].w;
        }

        int cur = 0;
        for (int it = 0; it < NT; it++) {
            __syncthreads();           // buffer[cur] visible to everyone
            if (it + 1 < NT) {
                int dk = (it + 1) * BK;
                #pragma unroll
                for (int r = 0; r < 2; r++) {
                    int f = t * 2 + r, row = f >> 2, ds = (f & 3) * 4;
                    zr[r] = *(const float4*)(Z + (size_t)(row0 + row) * D_DIM + dk + ds);
                    er[r] = *(const float4*)(E + (size_t)(col0 + row) * D_DIM + dk + ds);
                }
            }

            const float (*zsc)[BM] = Zs[cur];
            const float (*esc)[BN] = Es[cur];
            #pragma unroll
            for (int kk = 0; kk < BK; kk++) {
                float a[TM], b[TN];
                *(float4*)&a[0] = *(const float4*)&zsc[kk][ty * TM];
                *(float4*)&a[4] = *(const float4*)&zsc[kk][ty * TM + 4];
                *(float4*)&b[0] = *(const float4*)&esc[kk][tx * TN];
                *(float4*)&b[4] = *(const float4*)&esc[kk][tx * TN + 4];
                #pragma unroll
                for (int i = 0; i < TM; i++)
                    #pragma unroll
                    for (int j = 0; j < TN; j++)
                        acc[i][j] = fmaf(a[i], b[j], acc[i][j]);
            }

            if (it + 1 < NT) {
                int nb = cur ^ 1;
                #pragma unroll
                for (int r = 0; r < 2; r++) {
                    int f = t * 2 + r, row = f >> 2, ds = (f & 3) * 4;
                    Zs[nb][ds + 0][row] = zr[r].x; Zs[nb][ds + 1][row] = zr[r].y;
                    Zs[nb][ds + 2][row] = zr[r].z; Zs[nb][ds + 3][row] = zr[r].w;
                    Es[nb][ds + 0][row] = er[r].x; Es[nb][ds + 1][row] = er[r].y;
                    Es[nb][ds + 2][row] = er[r].z; Es[nb][ds + 3][row] = er[r].w;
                }
            }
            cur ^= 1;
        }

        // epilogue: distances + running argmin (first-min tie-break)
        #pragma unroll
        for (int i = 0; i < TM; i++) {
            float zn = zn_s[ty * TM + i];
            #pragma unroll
            for (int j = 0; j < TN; j++) {
                int   c = col0 + tx * TN + j;
                float d = (zn + en_s[tx * TN + j]) - 2.0f * acc[i][j];
                if (d < best[i] || (d == best[i] && c < bidx[i])) {
                    best[i] = d; bidx[i] = c;
                }
            }
        }
    }

    // reduce across the 16 column-group lanes sharing each row
    #pragma unroll
    for (int i = 0; i < TM; i++) {
        float v  = best[i];
        int   ix = bidx[i];
        #pragma unroll
        for (int o = 8; o > 0; o >>= 1) {
            float ov = __shfl_down_sync(0xffffffffu, v,  o, 16);
            int   oi = __shfl_down_sync(0xffffffffu, ix, o, 16);
            if (ov < v || (ov == v && oi < ix)) { v = ov; ix = oi; }
        }
        if (tx == 0) g_idx[row0 + ty * TM + i] = ix;
    }
}

// ---------------------------------------------------------------------------
// Gather quantized rows, emit straight-through output z + (q - z) with ref's
// fp32 rounding, per-row loss partials, and index-as-float tail.
// ---------------------------------------------------------------------------
__global__ void gather_kernel(const float* __restrict__ Z,
                              const float* __restrict__ E,
                              float* __restrict__ out, int out_size) {
    int row = blockIdx.x;
    int t   = threadIdx.x;   // 128
    int idx = g_idx[row];
    const float* e = E + (size_t)idx * D_DIM;
    const float* z = Z + (size_t)row * D_DIM;
    float* o = out + (size_t)row * D_DIM;

    double s = 0.0;
    #pragma unroll
    for (int i = 0; i < 4; i++) {
        int d = t + i * 128;
        float q  = e[d];
        float zc = z[d];
        float dq = q - zc;       // stopgrad(q) - z, also the ST residual
        o[d] = zc + dq;          // replicate fl(z + fl(q - z))
        s += (double)dq * (double)dq;
    }
    __shared__ double sh[128];
    sh[t] = s;
    __syncthreads();
    for (int o2 = 64; o2 > 0; o2 >>= 1) {
        if (t < o2) sh[t] += sh[t + o2];
        __syncthreads();
    }
    if (t == 0) {
        g_rowpart[row] = sh[0];
        if (out_size >= N_ROWS * D_DIM + 1 + N_ROWS)
            out[(size_t)N_ROWS * D_DIM + 1 + row] = (float)idx;
    }
}

__global__ void loss_kernel(float* __restrict__ out, int out_size) {
    __shared__ double sh[256];
    int t = threadIdx.x;
    double s = 0.0;
    for (int i = t; i < N_ROWS; i += 256) s += g_rowpart[i];
    sh[t] = s;
    __syncthreads();
    for (int o = 128; o > 0; o >>= 1) {
        if (t < o) sh[t] += sh[t + o];
        __syncthreads();
    }
    if (t == 0 && out_size >= N_ROWS * D_DIM + 1) {
        double m = sh[0] / ((double)N_ROWS * (double)D_DIM);
        out[(size_t)N_ROWS * D_DIM] = (float)(1.25 * m);  // q_loss + 0.25*e_loss
    }
}

// ---------------------------------------------------------------------------
extern "C" void kernel_launch(void* const* d_in, const int* in_sizes, int n_in,
                              void* d_out, int out_size) {
    const float* z = (const float*)d_in[0];
    const float* e = (const float*)d_in[1];
    // defensive: identify by size (z is N*D = 16777216, e is K*D = 4194304)
    if (n_in >= 2 && in_sizes[0] == K_CODES * D_DIM && in_sizes[1] == N_ROWS * D_DIM) {
        const float* tmp = z; z = e; e = tmp;
    }
    float* out = (float*)d_out;

    int norm_warps  = N_ROWS + K_CODES;
    int norm_blocks = (norm_warps * 32 + 255) / 256;
    norms_kernel<<<norm_blocks, 256>>>(z, e);
    argmin_kernel<<<N_ROWS / BM, NTHREADS>>>(z, e);
    gather_kernel<<<N_ROWS, 128>>>(z, e, out, out_size);
    loss_kernel<<<1, 256>>>(out, out_size);
}

// round 3
// speedup vs baseline: 2.8496x; 2.8496x over previous
#include <cuda_runtime.h>
#include <cstdint>

#define N_ROWS 32768
#define K_CODES 8192
#define D_DIM 512

#define BM 128
#define BN 128
#define BK 32
#define NCHUNKS 64          // K_CODES / BN
#define KITERS 16           // D_DIM / BK
#define PAD 36              // BK + 4 : conflict-free fragment LDS
#define MARGIN 4e-4f
#define NSHARDS 64
#define SHARD_CAP 65536
#define FLT_MAX_BITS 0x7f7fffff

// ---------------- scratch (static __device__, no allocs) ----------------
__device__ float  g_znorm[N_ROWS];
__device__ float  g_enorm[K_CODES];
__device__ unsigned long long g_best[N_ROWS];
__device__ int    g_cand[NSHARDS][SHARD_CAP];
__device__ int    g_ncand[NSHARDS];
__device__ double g_rowpart[N_ROWS];

// ---------------- helpers ----------------
__device__ __forceinline__ uint32_t smem_u32(const void* p) {
    uint32_t a;
    asm("{ .reg .u64 t; cvta.to.shared.u64 t, %1; cvt.u32.u64 %0, t; }" : "=r"(a) : "l"(p));
    return a;
}
__device__ __forceinline__ void cpasync16(uint32_t dst, const void* src) {
    asm volatile("cp.async.cg.shared.global [%0], [%1], 16;" :: "r"(dst), "l"(src));
}
#define CP_COMMIT() asm volatile("cp.async.commit_group;" ::: "memory")
#define CP_WAIT0()  asm volatile("cp.async.wait_group 0;" ::: "memory")

// m16n8k8 tf32 HMMA (sm_80 base feature; raw fp32 bits => tf32 truncation)
__device__ __forceinline__ void mma_tf32(float* d, const uint32_t* a, const uint32_t* b) {
    asm volatile("mma.sync.aligned.m16n8k8.row.col.f32.tf32.tf32.f32 "
        "{%0,%1,%2,%3}, {%4,%5,%6,%7}, {%8,%9}, {%0,%1,%2,%3};"
        : "+f"(d[0]), "+f"(d[1]), "+f"(d[2]), "+f"(d[3])
        : "r"(a[0]), "r"(a[1]), "r"(a[2]), "r"(a[3]), "r"(b[0]), "r"(b[1]));
}

// ---------------------------------------------------------------------------
__global__ void init_kernel() {
    int t = blockIdx.x * blockDim.x + threadIdx.x;
    if (t < NSHARDS) g_ncand[t] = 0;
    for (int i = t; i < N_ROWS; i += gridDim.x * blockDim.x)
        g_best[i] = 0xFFFFFFFFFFFFFFFFULL;
}

__global__ void norms_kernel(const float* __restrict__ z, const float* __restrict__ e) {
    int gw = (blockIdx.x * blockDim.x + threadIdx.x) >> 5;
    int lane = threadIdx.x & 31;
    if (gw >= N_ROWS + K_CODES) return;
    const float* p = (gw < N_ROWS) ? (z + (size_t)gw * D_DIM)
                                   : (e + (size_t)(gw - N_ROWS) * D_DIM);
    float acc = 0.0f;
    #pragma unroll
    for (int i = lane; i < D_DIM; i += 32) { float v = p[i]; acc = fmaf(v, v, acc); }
    #pragma unroll
    for (int o = 16; o > 0; o >>= 1) acc += __shfl_down_sync(0xffffffffu, acc, o);
    if (lane == 0) { if (gw < N_ROWS) g_znorm[gw] = acc; else g_enorm[gw - N_ROWS] = acc; }
}

// ---------------------------------------------------------------------------
// tf32 mma.sync GEMM + running per-row best + margin candidate push.
// 8 warps as 2(m) x 4(n); warp tile 64x32; 2-stage cp.async pipeline.
// ---------------------------------------------------------------------------
__global__ __launch_bounds__(256, 2)
void vq_mma_kernel(const float* __restrict__ Z, const float* __restrict__ E) {
    extern __shared__ float sm_f[];
    float (*Zs)[BM][PAD] = reinterpret_cast<float (*)[BM][PAD]>(sm_f);
    float (*Es)[BN][PAD] = reinterpret_cast<float (*)[BN][PAD]>(sm_f + 2 * BM * PAD);
    int* s_rowbest = reinterpret_cast<int*>(sm_f + 4 * BM * PAD);

    const int tid = threadIdx.x;
    const int wid = tid >> 5;
    const int l   = tid & 31;
    const int warp_m = wid >> 2;        // 0..1
    const int warp_n = wid & 3;         // 0..3
    const int l4 = l >> 2;              // 0..7
    const int kc = l & 3;               // 0..3
    const int row0 = blockIdx.x * BM;
    const int mrow = warp_m * 64 + l4;
    const int ncol = warp_n * 32 + l4;
    const int shard = blockIdx.x & (NSHARDS - 1);

    const uint32_t zs_base = smem_u32(&Zs[0][0][0]);
    const uint32_t es_base = smem_u32(&Es[0][0][0]);

    if (tid < BM) s_rowbest[tid] = FLT_MAX_BITS;

    // preload z norms for this thread's 8 rows
    float zn[8];
    #pragma unroll
    for (int mi = 0; mi < 4; mi++)
        #pragma unroll
        for (int hi = 0; hi < 2; hi++)
            zn[mi * 2 + hi] = g_znorm[row0 + warp_m * 64 + mi * 16 + hi * 8 + l4];

    __syncthreads();

    for (int c = 0; c < NCHUNKS; c++) {
        float acc[4][4][4];
        #pragma unroll
        for (int mi = 0; mi < 4; mi++)
            #pragma unroll
            for (int ni = 0; ni < 4; ni++)
                #pragma unroll
                for (int r = 0; r < 4; r++) acc[mi][ni][r] = 0.0f;

        // prologue: k-iter 0 into stage 0
        {
            const float* Zg = Z + (size_t)row0 * D_DIM;
            const float* Eg = E + (size_t)(c * BN) * D_DIM;
            #pragma unroll
            for (int i = 0; i < 4; i++) {
                int u = tid + i * 256, r = u >> 3, s = u & 7;
                cpasync16(zs_base + r * (PAD * 4) + s * 16, Zg + (size_t)r * D_DIM + s * 4);
                cpasync16(es_base + r * (PAD * 4) + s * 16, Eg + (size_t)r * D_DIM + s * 4);
            }
            CP_COMMIT();
        }

        for (int it = 0; it < KITERS; it++) {
            CP_WAIT0();
            __syncthreads();
            if (it + 1 < KITERS) {
                const int st = (it + 1) & 1;
                const int k0 = (it + 1) * BK;
                const float* Zg = Z + (size_t)row0 * D_DIM + k0;
                const float* Eg = E + (size_t)(c * BN) * D_DIM + k0;
                const uint32_t zb = zs_base + st * (BM * PAD * 4);
                const uint32_t eb = es_base + st * (BN * PAD * 4);
                #pragma unroll
                for (int i = 0; i < 4; i++) {
                    int u = tid + i * 256, r = u >> 3, s = u & 7;
                    cpasync16(zb + r * (PAD * 4) + s * 16, Zg + (size_t)r * D_DIM + s * 4);
                    cpasync16(eb + r * (PAD * 4) + s * 16, Eg + (size_t)r * D_DIM + s * 4);
                }
                CP_COMMIT();
            }
            // compute on stage it&1
            const float (*Zt)[PAD] = Zs[it & 1];
            const float (*Et)[PAD] = Es[it & 1];
            #pragma unroll
            for (int ks = 0; ks < 4; ks++) {
                const int kb = ks * 8 + kc;
                uint32_t a[4][4], b[4][2];
                #pragma unroll
                for (int mi = 0; mi < 4; mi++) {
                    const int r = mrow + mi * 16;
                    a[mi][0] = __float_as_uint(Zt[r][kb]);
                    a[mi][1] = __float_as_uint(Zt[r + 8][kb]);
                    a[mi][2] = __float_as_uint(Zt[r][kb + 4]);
                    a[mi][3] = __float_as_uint(Zt[r + 8][kb + 4]);
                }
                #pragma unroll
                for (int ni = 0; ni < 4; ni++) {
                    const int n = ncol + ni * 8;
                    b[ni][0] = __float_as_uint(Et[n][kb]);
                    b[ni][1] = __float_as_uint(Et[n][kb + 4]);
                }
                #pragma unroll
                for (int mi = 0; mi < 4; mi++)
                    #pragma unroll
                    for (int ni = 0; ni < 4; ni++)
                        mma_tf32(acc[mi][ni], a[mi], b[ni]);
            }
        }

        // ---------- epilogue pass 1: per-row running min ----------
        const int colg0 = c * BN + warp_n * 32 + kc * 2;
        float dmin[8];
        #pragma unroll
        for (int i = 0; i < 8; i++) dmin[i] = 3.4028235e38f;
        #pragma unroll
        for (int ni = 0; ni < 4; ni++) {
            float en0 = __ldg(&g_enorm[colg0 + ni * 8]);
            float en1 = __ldg(&g_enorm[colg0 + ni * 8 + 1]);
            #pragma unroll
            for (int mi = 0; mi < 4; mi++) {
                float d0 = (zn[mi * 2] + en0)     - 2.0f * acc[mi][ni][0];
                float d1 = (zn[mi * 2] + en1)     - 2.0f * acc[mi][ni][1];
                float d2 = (zn[mi * 2 + 1] + en0) - 2.0f * acc[mi][ni][2];
                float d3 = (zn[mi * 2 + 1] + en1) - 2.0f * acc[mi][ni][3];
                dmin[mi * 2]     = fminf(dmin[mi * 2], fminf(d0, d1));
                dmin[mi * 2 + 1] = fminf(dmin[mi * 2 + 1], fminf(d2, d3));
            }
        }
        #pragma unroll
        for (int i = 0; i < 8; i++) {
            dmin[i] = fminf(dmin[i], __shfl_xor_sync(0xffffffffu, dmin[i], 1));
            dmin[i] = fminf(dmin[i], __shfl_xor_sync(0xffffffffu, dmin[i], 2));
        }
        if (kc == 0) {
            #pragma unroll
            for (int mi = 0; mi < 4; mi++) {
                atomicMin(&s_rowbest[warp_m * 64 + mi * 16 + l4],     __float_as_int(dmin[mi * 2]));
                atomicMin(&s_rowbest[warp_m * 64 + mi * 16 + 8 + l4], __float_as_int(dmin[mi * 2 + 1]));
            }
        }
        __syncthreads();

        // ---------- epilogue pass 2: margin candidate push ----------
        #pragma unroll
        for (int ni = 0; ni < 4; ni++) {
            float en0 = __ldg(&g_enorm[colg0 + ni * 8]);
            float en1 = __ldg(&g_enorm[colg0 + ni * 8 + 1]);
            #pragma unroll
            for (int mi = 0; mi < 4; mi++) {
                const int rl0 = warp_m * 64 + mi * 16 + l4;
                const int rl1 = rl0 + 8;
                const float b0 = __int_as_float(s_rowbest[rl0]) + MARGIN;
                const float b1 = __int_as_float(s_rowbest[rl1]) + MARGIN;
                float d0 = (zn[mi * 2] + en0)     - 2.0f * acc[mi][ni][0];
                float d1 = (zn[mi * 2] + en1)     - 2.0f * acc[mi][ni][1];
                float d2 = (zn[mi * 2 + 1] + en0) - 2.0f * acc[mi][ni][2];
                float d3 = (zn[mi * 2 + 1] + en1) - 2.0f * acc[mi][ni][3];
                if (d0 < b0) { int p = atomicAdd(&g_ncand[shard], 1);
                    if (p < SHARD_CAP) g_cand[shard][p] = ((row0 + rl0) << 13) | (colg0 + ni * 8); }
                if (d1 < b0) { int p = atomicAdd(&g_ncand[shard], 1);
                    if (p < SHARD_CAP) g_cand[shard][p] = ((row0 + rl0) << 13) | (colg0 + ni * 8 + 1); }
                if (d2 < b1) { int p = atomicAdd(&g_ncand[shard], 1);
                    if (p < SHARD_CAP) g_cand[shard][p] = ((row0 + rl1) << 13) | (colg0 + ni * 8); }
                if (d3 < b1) { int p = atomicAdd(&g_ncand[shard], 1);
                    if (p < SHARD_CAP) g_cand[shard][p] = ((row0 + rl1) << 13) | (colg0 + ni * 8 + 1); }
            }
        }
        // next chunk's prologue writes stage 0 (last read at it=14, protected
        // by the it=15 syncthreads); pass2 touches no tile smem — no barrier needed.
    }
}

// ---------------------------------------------------------------------------
// Exact fp32 refinement of candidates; atomicMin picks (min dist, min idx).
// ---------------------------------------------------------------------------
__global__ void refine_kernel(const float* __restrict__ Z, const float* __restrict__ E) {
    const int nwarps = (gridDim.x * blockDim.x) >> 5;
    const int gw     = (blockIdx.x * blockDim.x + threadIdx.x) >> 5;
    const int lane   = threadIdx.x & 31;

    for (int s = 0; s < NSHARDS; s++) {
        int n = g_ncand[s];
        if (n > SHARD_CAP) n = SHARD_CAP;
        for (int i = gw; i < n; i += nwarps) {
            int cd  = g_cand[s][i];
            int row = cd >> 13;
            int idx = cd & (K_CODES - 1);
            const float* z = Z + (size_t)row * D_DIM;
            const float* e = E + (size_t)idx * D_DIM;
            float dot = 0.0f;
            const int k0 = lane * 16;
            #pragma unroll
            for (int k = 0; k < 16; k++) dot = fmaf(z[k0 + k], e[k0 + k], dot);
            #pragma unroll
            for (int o = 16; o > 0; o >>= 1) dot += __shfl_down_sync(0xffffffffu, dot, o);
            if (lane == 0) {
                float d = (g_znorm[row] + g_enorm[idx]) - 2.0f * dot;
                unsigned long long key = ((unsigned long long)__float_as_uint(d) << 32) | (unsigned)idx;
                atomicMin(&g_best[row], key);
            }
        }
    }
}

// ---------------------------------------------------------------------------
__global__ void gather_kernel(const float* __restrict__ Z, const float* __restrict__ E,
                              float* __restrict__ out, int out_size) {
    int row = blockIdx.x;
    int t   = threadIdx.x;   // 128
    int idx = (int)(g_best[row] & 0xFFFFFFFFull) & (K_CODES - 1);
    const float* e = E + (size_t)idx * D_DIM;
    const float* z = Z + (size_t)row * D_DIM;
    float* o = out + (size_t)row * D_DIM;

    double s = 0.0;
    #pragma unroll
    for (int i = 0; i < 4; i++) {
        int d = t + i * 128;
        float q  = e[d];
        float zc = z[d];
        float dq = q - zc;
        o[d] = zc + dq;
        s += (double)dq * (double)dq;
    }
    __shared__ double sh[128];
    sh[t] = s;
    __syncthreads();
    for (int o2 = 64; o2 > 0; o2 >>= 1) { if (t < o2) sh[t] += sh[t + o2]; __syncthreads(); }
    if (t == 0) {
        g_rowpart[row] = sh[0];
        if (out_size >= N_ROWS * D_DIM + 1 + N_ROWS)
            out[(size_t)N_ROWS * D_DIM + 1 + row] = (float)idx;
    }
}

__global__ void loss_kernel(float* __restrict__ out, int out_size) {
    __shared__ double sh[256];
    int t = threadIdx.x;
    double s = 0.0;
    for (int i = t; i < N_ROWS; i += 256) s += g_rowpart[i];
    sh[t] = s;
    __syncthreads();
    for (int o = 128; o > 0; o >>= 1) { if (t < o) sh[t] += sh[t + o]; __syncthreads(); }
    if (t == 0 && out_size >= N_ROWS * D_DIM + 1) {
        double m = sh[0] / ((double)N_ROWS * (double)D_DIM);
        out[(size_t)N_ROWS * D_DIM] = (float)(1.25 * m);
    }
}

// ---------------------------------------------------------------------------
extern "C" void kernel_launch(void* const* d_in, const int* in_sizes, int n_in,
                              void* d_out, int out_size) {
    const float* z = (const float*)d_in[0];
    const float* e = (const float*)d_in[1];
    if (n_in >= 2 && in_sizes[0] == K_CODES * D_DIM && in_sizes[1] == N_ROWS * D_DIM) {
        const float* tmp = z; z = e; e = tmp;
    }
    float* out = (float*)d_out;

    const int smem_bytes = 4 * BM * PAD * 4 + BM * 4;   // 74240
    cudaFuncSetAttribute(vq_mma_kernel, cudaFuncAttributeMaxDynamicSharedMemorySize, smem_bytes);

    init_kernel<<<256, 256>>>();
    int norm_blocks = ((N_ROWS + K_CODES) * 32 + 255) / 256;
    norms_kernel<<<norm_blocks, 256>>>(z, e);
    vq_mma_kernel<<<N_ROWS / BM, 256, smem_bytes>>>(z, e);
    refine_kernel<<<1024, 256>>>(z, e);
    gather_kernel<<<N_ROWS, 128>>>(z, e, out, out_size);
    loss_kernel<<<1, 256>>>(out, out_size);
}

// round 4
// speedup vs baseline: 3.4280x; 1.2029x over previous
#include <cuda_runtime.h>
#include <cstdint>

#define N_ROWS 32768
#define K_CODES 8192
#define D_DIM 512

#define BM 128
#define BN 128
#define BK 32
#define STAGES 3
#define NCHUNKS 64          // K_CODES / BN
#define KITERS 16           // D_DIM / BK
#define PAD 36              // BK + 4 : conflict-free fragment LDS
#define MARGIN 4e-4f
#define NSHARDS 64
#define SHARD_CAP 65536
#define FLT_MAX_BITS 0x7f7fffff

// ---------------- scratch (static __device__, no allocs) ----------------
__device__ float  g_znorm[N_ROWS];
__device__ float  g_enorm[K_CODES];
__device__ unsigned long long g_best[N_ROWS];
__device__ int    g_cand[NSHARDS][SHARD_CAP];
__device__ int    g_ncand[NSHARDS];
__device__ double g_rowpart[N_ROWS];

// ---------------- helpers ----------------
__device__ __forceinline__ uint32_t smem_u32(const void* p) {
    uint32_t a;
    asm("{ .reg .u64 t; cvta.to.shared.u64 t, %1; cvt.u32.u64 %0, t; }" : "=r"(a) : "l"(p));
    return a;
}
__device__ __forceinline__ void cpasync16(uint32_t dst, const void* src) {
    asm volatile("cp.async.cg.shared.global [%0], [%1], 16;" :: "r"(dst), "l"(src));
}
#define CP_COMMIT() asm volatile("cp.async.commit_group;" ::: "memory")
#define CP_WAITG1() asm volatile("cp.async.wait_group 1;" ::: "memory")

// m16n8k8 tf32 HMMA (sm_80 base feature; raw fp32 bits => tf32 truncation)
__device__ __forceinline__ void mma_tf32(float* d, const uint32_t* a, const uint32_t* b) {
    asm volatile("mma.sync.aligned.m16n8k8.row.col.f32.tf32.tf32.f32 "
        "{%0,%1,%2,%3}, {%4,%5,%6,%7}, {%8,%9}, {%0,%1,%2,%3};"
        : "+f"(d[0]), "+f"(d[1]), "+f"(d[2]), "+f"(d[3])
        : "r"(a[0]), "r"(a[1]), "r"(a[2]), "r"(a[3]), "r"(b[0]), "r"(b[1]));
}

// ---------------------------------------------------------------------------
__global__ void init_kernel() {
    int t = blockIdx.x * blockDim.x + threadIdx.x;
    if (t < NSHARDS) g_ncand[t] = 0;
    for (int i = t; i < N_ROWS; i += gridDim.x * blockDim.x)
        g_best[i] = 0xFFFFFFFFFFFFFFFFULL;
}

__global__ void norms_kernel(const float* __restrict__ z, const float* __restrict__ e) {
    int gw = (blockIdx.x * blockDim.x + threadIdx.x) >> 5;
    int lane = threadIdx.x & 31;
    if (gw >= N_ROWS + K_CODES) return;
    const float* p = (gw < N_ROWS) ? (z + (size_t)gw * D_DIM)
                                   : (e + (size_t)(gw - N_ROWS) * D_DIM);
    float acc = 0.0f;
    #pragma unroll
    for (int i = lane; i < D_DIM; i += 32) { float v = p[i]; acc = fmaf(v, v, acc); }
    #pragma unroll
    for (int o = 16; o > 0; o >>= 1) acc += __shfl_down_sync(0xffffffffu, acc, o);
    if (lane == 0) { if (gw < N_ROWS) g_znorm[gw] = acc; else g_enorm[gw - N_ROWS] = acc; }
}

// ---------------------------------------------------------------------------
// tf32 mma.sync GEMM + running per-row best + margin candidate push.
// 8 warps as 2(m) x 4(n); warp tile 64x32; 3-stage cp.async pipeline.
// ---------------------------------------------------------------------------
__global__ __launch_bounds__(256, 2)
void vq_mma_kernel(const float* __restrict__ Z, const float* __restrict__ E) {
    extern __shared__ float sm_f[];
    // layout: STAGES x [ Zs(BM x PAD) ; Es(BN x PAD) ]
    int* s_rowbest = reinterpret_cast<int*>(sm_f + STAGES * (BM + BN) * PAD);

    const int tid = threadIdx.x;
    const int wid = tid >> 5;
    const int l   = tid & 31;
    const int warp_m = wid >> 2;        // 0..1
    const int warp_n = wid & 3;         // 0..3
    const int l4 = l >> 2;              // 0..7
    const int kc = l & 3;               // 0..3
    const int row0 = blockIdx.x * BM;
    const int mrow = warp_m * 64 + l4;
    const int ncol = warp_n * 32 + l4;
    const int shard = blockIdx.x & (NSHARDS - 1);

    const uint32_t sm_base   = smem_u32(sm_f);
    const int      stage_fb  = (BM + BN) * PAD;               // floats per stage
    const uint32_t stage_b   = (uint32_t)stage_fb * 4;        // bytes per stage
    const uint32_t eoff_b    = (uint32_t)(BM * PAD) * 4;      // E offset within stage

    if (tid < BM) s_rowbest[tid] = FLT_MAX_BITS;

    // preload z norms for this thread's 8 rows
    float zn[8];
    #pragma unroll
    for (int mi = 0; mi < 4; mi++)
        #pragma unroll
        for (int hi = 0; hi < 2; hi++)
            zn[mi * 2 + hi] = g_znorm[row0 + warp_m * 64 + mi * 16 + hi * 8 + l4];

    __syncthreads();

    for (int c = 0; c < NCHUNKS; c++) {
        float acc[4][4][4];
        #pragma unroll
        for (int mi = 0; mi < 4; mi++)
            #pragma unroll
            for (int ni = 0; ni < 4; ni++)
                #pragma unroll
                for (int r = 0; r < 4; r++) acc[mi][ni][r] = 0.0f;

        const float* Zg0 = Z + (size_t)row0 * D_DIM;
        const float* Eg0 = E + (size_t)(c * BN) * D_DIM;

        // prologue: load k-iters 0 and 1 into stages 0,1 (separate groups)
        #pragma unroll
        for (int pre = 0; pre < 2; pre++) {
            const int k0 = pre * BK;
            const uint32_t zb = sm_base + (uint32_t)pre * stage_b;
            const uint32_t eb = zb + eoff_b;
            #pragma unroll
            for (int i = 0; i < 4; i++) {
                int u = tid + i * 256, r = u >> 3, s = u & 7;
                cpasync16(zb + r * (PAD * 4) + s * 16, Zg0 + (size_t)r * D_DIM + k0 + s * 4);
                cpasync16(eb + r * (PAD * 4) + s * 16, Eg0 + (size_t)r * D_DIM + k0 + s * 4);
            }
            CP_COMMIT();
        }

        for (int it = 0; it < KITERS; it++) {
            CP_WAITG1();            // group for iter `it` complete (<=1 pending)
            __syncthreads();
            if (it + 2 < KITERS) {  // prefetch iter it+2 into stage (it+2)%3
                const int st = (it + 2) % STAGES;
                const int k0 = (it + 2) * BK;
                const uint32_t zb = sm_base + (uint32_t)st * stage_b;
                const uint32_t eb = zb + eoff_b;
                #pragma unroll
                for (int i = 0; i < 4; i++) {
                    int u = tid + i * 256, r = u >> 3, s = u & 7;
                    cpasync16(zb + r * (PAD * 4) + s * 16, Zg0 + (size_t)r * D_DIM + k0 + s * 4);
                    cpasync16(eb + r * (PAD * 4) + s * 16, Eg0 + (size_t)r * D_DIM + k0 + s * 4);
                }
                CP_COMMIT();
            }
            // compute on stage it%3
            const float (*Zt)[PAD] =
                reinterpret_cast<const float (*)[PAD]>(sm_f + (it % STAGES) * stage_fb);
            const float (*Et)[PAD] =
                reinterpret_cast<const float (*)[PAD]>(sm_f + (it % STAGES) * stage_fb + BM * PAD);
            #pragma unroll
            for (int ks = 0; ks < 4; ks++) {
                const int kb = ks * 8 + kc;
                uint32_t a[4][4], b[4][2];
                #pragma unroll
                for (int mi = 0; mi < 4; mi++) {
                    const int r = mrow + mi * 16;
                    a[mi][0] = __float_as_uint(Zt[r][kb]);
                    a[mi][1] = __float_as_uint(Zt[r + 8][kb]);
                    a[mi][2] = __float_as_uint(Zt[r][kb + 4]);
                    a[mi][3] = __float_as_uint(Zt[r + 8][kb + 4]);
                }
                #pragma unroll
                for (int ni = 0; ni < 4; ni++) {
                    const int n = ncol + ni * 8;
                    b[ni][0] = __float_as_uint(Et[n][kb]);
                    b[ni][1] = __float_as_uint(Et[n][kb + 4]);
                }
                #pragma unroll
                for (int mi = 0; mi < 4; mi++)
                    #pragma unroll
                    for (int ni = 0; ni < 4; ni++)
                        mma_tf32(acc[mi][ni], a[mi], b[ni]);
            }
        }

        // ---------- epilogue pass 1: per-row running min ----------
        const int colg0 = c * BN + warp_n * 32 + kc * 2;
        float dmin[8];
        #pragma unroll
        for (int i = 0; i < 8; i++) dmin[i] = 3.4028235e38f;
        #pragma unroll
        for (int ni = 0; ni < 4; ni++) {
            float en0 = __ldg(&g_enorm[colg0 + ni * 8]);
            float en1 = __ldg(&g_enorm[colg0 + ni * 8 + 1]);
            #pragma unroll
            for (int mi = 0; mi < 4; mi++) {
                float d0 = (zn[mi * 2] + en0)     - 2.0f * acc[mi][ni][0];
                float d1 = (zn[mi * 2] + en1)     - 2.0f * acc[mi][ni][1];
                float d2 = (zn[mi * 2 + 1] + en0) - 2.0f * acc[mi][ni][2];
                float d3 = (zn[mi * 2 + 1] + en1) - 2.0f * acc[mi][ni][3];
                dmin[mi * 2]     = fminf(dmin[mi * 2], fminf(d0, d1));
                dmin[mi * 2 + 1] = fminf(dmin[mi * 2 + 1], fminf(d2, d3));
            }
        }
        #pragma unroll
        for (int i = 0; i < 8; i++) {
            dmin[i] = fminf(dmin[i], __shfl_xor_sync(0xffffffffu, dmin[i], 1));
            dmin[i] = fminf(dmin[i], __shfl_xor_sync(0xffffffffu, dmin[i], 2));
        }
        if (kc == 0) {
            #pragma unroll
            for (int mi = 0; mi < 4; mi++) {
                atomicMin(&s_rowbest[warp_m * 64 + mi * 16 + l4],     __float_as_int(dmin[mi * 2]));
                atomicMin(&s_rowbest[warp_m * 64 + mi * 16 + 8 + l4], __float_as_int(dmin[mi * 2 + 1]));
            }
        }
        __syncthreads();

        // ---------- epilogue pass 2: margin candidate push ----------
        #pragma unroll
        for (int ni = 0; ni < 4; ni++) {
            float en0 = __ldg(&g_enorm[colg0 + ni * 8]);
            float en1 = __ldg(&g_enorm[colg0 + ni * 8 + 1]);
            #pragma unroll
            for (int mi = 0; mi < 4; mi++) {
                const int rl0 = warp_m * 64 + mi * 16 + l4;
                const int rl1 = rl0 + 8;
                const float b0 = __int_as_float(s_rowbest[rl0]) + MARGIN;
                const float b1 = __int_as_float(s_rowbest[rl1]) + MARGIN;
                float d0 = (zn[mi * 2] + en0)     - 2.0f * acc[mi][ni][0];
                float d1 = (zn[mi * 2] + en1)     - 2.0f * acc[mi][ni][1];
                float d2 = (zn[mi * 2 + 1] + en0) - 2.0f * acc[mi][ni][2];
                float d3 = (zn[mi * 2 + 1] + en1) - 2.0f * acc[mi][ni][3];
                if (d0 < b0) { int p = atomicAdd(&g_ncand[shard], 1);
                    if (p < SHARD_CAP) g_cand[shard][p] = ((row0 + rl0) << 13) | (colg0 + ni * 8); }
                if (d1 < b0) { int p = atomicAdd(&g_ncand[shard], 1);
                    if (p < SHARD_CAP) g_cand[shard][p] = ((row0 + rl0) << 13) | (colg0 + ni * 8 + 1); }
                if (d2 < b1) { int p = atomicAdd(&g_ncand[shard], 1);
                    if (p < SHARD_CAP) g_cand[shard][p] = ((row0 + rl1) << 13) | (colg0 + ni * 8); }
                if (d3 < b1) { int p = atomicAdd(&g_ncand[shard], 1);
                    if (p < SHARD_CAP) g_cand[shard][p] = ((row0 + rl1) << 13) | (colg0 + ni * 8 + 1); }
            }
        }
        // pass-1's __syncthreads ordered all it=15 computes before any warp
        // reaches the next chunk's prologue stores; pass 2 touches no tile smem.
    }
}

// ---------------------------------------------------------------------------
// Exact fp32 refinement; coalesced float4 loads (4 lines per LDG, not 32).
// ---------------------------------------------------------------------------
__global__ void refine_kernel(const float* __restrict__ Z, const float* __restrict__ E) {
    const int nwarps = (gridDim.x * blockDim.x) >> 5;
    const int gw     = (blockIdx.x * blockDim.x + threadIdx.x) >> 5;
    const int lane   = threadIdx.x & 31;

    for (int s = 0; s < NSHARDS; s++) {
        int n = g_ncand[s];
        if (n > SHARD_CAP) n = SHARD_CAP;
        for (int i = gw; i < n; i += nwarps) {
            int cd  = g_cand[s][i];
            int row = cd >> 13;
            int idx = cd & (K_CODES - 1);
            const float4* z4 = reinterpret_cast<const float4*>(Z + (size_t)row * D_DIM);
            const float4* e4 = reinterpret_cast<const float4*>(E + (size_t)idx * D_DIM);
            float4 zv[4], ev[4];
            #pragma unroll
            for (int j = 0; j < 4; j++) {           // coalesced: lane-major
                zv[j] = z4[j * 32 + lane];
                ev[j] = e4[j * 32 + lane];
            }
            float dot = 0.0f;
            #pragma unroll
            for (int j = 0; j < 4; j++) {
                dot = fmaf(zv[j].x, ev[j].x, dot);
                dot = fmaf(zv[j].y, ev[j].y, dot);
                dot = fmaf(zv[j].z, ev[j].z, dot);
                dot = fmaf(zv[j].w, ev[j].w, dot);
            }
            #pragma unroll
            for (int o = 16; o > 0; o >>= 1) dot += __shfl_down_sync(0xffffffffu, dot, o);
            if (lane == 0) {
                float d = (g_znorm[row] + g_enorm[idx]) - 2.0f * dot;
                unsigned long long key = ((unsigned long long)__float_as_uint(d) << 32) | (unsigned)idx;
                atomicMin(&g_best[row], key);
            }
        }
    }
}

// ---------------------------------------------------------------------------
__global__ void gather_kernel(const float* __restrict__ Z, const float* __restrict__ E,
                              float* __restrict__ out, int out_size) {
    int row = blockIdx.x;
    int t   = threadIdx.x;   // 128
    int idx = (int)(g_best[row] & 0xFFFFFFFFull) & (K_CODES - 1);
    const float* e = E + (size_t)idx * D_DIM;
    const float* z = Z + (size_t)row * D_DIM;
    float* o = out + (size_t)row * D_DIM;

    double s = 0.0;
    #pragma unroll
    for (int i = 0; i < 4; i++) {
        int d = t + i * 128;
        float q  = e[d];
        float zc = z[d];
        float dq = q - zc;
        o[d] = zc + dq;
        s += (double)dq * (double)dq;
    }
    __shared__ double sh[128];
    sh[t] = s;
    __syncthreads();
    for (int o2 = 64; o2 > 0; o2 >>= 1) { if (t < o2) sh[t] += sh[t + o2]; __syncthreads(); }
    if (t == 0) {
        g_rowpart[row] = sh[0];
        if (out_size >= N_ROWS * D_DIM + 1 + N_ROWS)
            out[(size_t)N_ROWS * D_DIM + 1 + row] = (float)idx;
    }
}

__global__ void loss_kernel(float* __restrict__ out, int out_size) {
    __shared__ double sh[256];
    int t = threadIdx.x;
    double s = 0.0;
    for (int i = t; i < N_ROWS; i += 256) s += g_rowpart[i];
    sh[t] = s;
    __syncthreads();
    for (int o = 128; o > 0; o >>= 1) { if (t < o) sh[t] += sh[t + o]; __syncthreads(); }
    if (t == 0 && out_size >= N_ROWS * D_DIM + 1) {
        double m = sh[0] / ((double)N_ROWS * (double)D_DIM);
        out[(size_t)N_ROWS * D_DIM] = (float)(1.25 * m);
    }
}

// ---------------------------------------------------------------------------
extern "C" void kernel_launch(void* const* d_in, const int* in_sizes, int n_in,
                              void* d_out, int out_size) {
    const float* z = (const float*)d_in[0];
    const float* e = (const float*)d_in[1];
    if (n_in >= 2 && in_sizes[0] == K_CODES * D_DIM && in_sizes[1] == N_ROWS * D_DIM) {
        const float* tmp = z; z = e; e = tmp;
    }
    float* out = (float*)d_out;

    const int smem_bytes = STAGES * (BM + BN) * PAD * 4 + BM * 4;   // 111104
    cudaFuncSetAttribute(vq_mma_kernel, cudaFuncAttributeMaxDynamicSharedMemorySize, smem_bytes);

    init_kernel<<<256, 256>>>();
    int norm_blocks = ((N_ROWS + K_CODES) * 32 + 255) / 256;
    norms_kernel<<<norm_blocks, 256>>>(z, e);
    vq_mma_kernel<<<N_ROWS / BM, 256, smem_bytes>>>(z, e);
    refine_kernel<<<1024, 256>>>(z, e);
    gather_kernel<<<N_ROWS, 128>>>(z, e, out, out_size);
    loss_kernel<<<1, 256>>>(out, out_size);
}

// round 5
// speedup vs baseline: 5.0947x; 1.4862x over previous
#include <cuda_runtime.h>
#include <cuda_bf16.h>
#include <cstdint>

#define N_ROWS 32768
#define K_CODES 8192
#define D_DIM 512

#define BM 128
#define BN 128
#define BKE 64              // bf16 k-elems per tile
#define STAGES 3
#define NCHUNKS 64          // K_CODES / BN
#define KITERS 8            // D_DIM / BKE
#define RSU 36              // row stride in uint32 (64/2 + 4 pad) = 144 B
#define MARGIN 1.2e-3f
#define NSHARDS 64
#define SHARD_CAP 65536
#define FLT_MAX_BITS 0x7f7fffff

#define ZPAIRS (N_ROWS * D_DIM / 2)
#define EPAIRS (K_CODES * D_DIM / 2)

// ---------------- scratch (static __device__, no allocs) ----------------
__device__ float  g_znorm[N_ROWS];
__device__ float  g_enorm[K_CODES];
__device__ uint32_t g_zbf[ZPAIRS];   // packed bf16x2
__device__ uint32_t g_ebf[EPAIRS];
__device__ unsigned long long g_best[N_ROWS];
__device__ int    g_cand[NSHARDS][SHARD_CAP];
__device__ int    g_ncand[NSHARDS];
__device__ double g_rowpart[N_ROWS];

// ---------------- helpers ----------------
__device__ __forceinline__ uint32_t smem_u32(const void* p) {
    uint32_t a;
    asm("{ .reg .u64 t; cvta.to.shared.u64 t, %1; cvt.u32.u64 %0, t; }" : "=r"(a) : "l"(p));
    return a;
}
__device__ __forceinline__ void cpasync16(uint32_t dst, const void* src) {
    asm volatile("cp.async.cg.shared.global [%0], [%1], 16;" :: "r"(dst), "l"(src));
}
#define CP_COMMIT() asm volatile("cp.async.commit_group;" ::: "memory")
#define CP_WAITG1() asm volatile("cp.async.wait_group 1;" ::: "memory")
#define CP_WAIT0()  asm volatile("cp.async.wait_group 0;" ::: "memory")

// m16n8k16 bf16 HMMA (sm_80 base feature)
__device__ __forceinline__ void mma_bf16(float* d, const uint32_t* a, const uint32_t* b) {
    asm volatile("mma.sync.aligned.m16n8k16.row.col.f32.bf16.bf16.f32 "
        "{%0,%1,%2,%3}, {%4,%5,%6,%7}, {%8,%9}, {%0,%1,%2,%3};"
        : "+f"(d[0]), "+f"(d[1]), "+f"(d[2]), "+f"(d[3])
        : "r"(a[0]), "r"(a[1]), "r"(a[2]), "r"(a[3]), "r"(b[0]), "r"(b[1]));
}

// ---------------------------------------------------------------------------
__global__ void init_kernel() {
    int t = blockIdx.x * blockDim.x + threadIdx.x;
    if (t < NSHARDS) g_ncand[t] = 0;
    for (int i = t; i < N_ROWS; i += gridDim.x * blockDim.x)
        g_best[i] = 0xFFFFFFFFFFFFFFFFULL;
}

__global__ void convert_kernel(const float* __restrict__ Z, const float* __restrict__ E) {
    const int stride = gridDim.x * blockDim.x;
    int t = blockIdx.x * blockDim.x + threadIdx.x;
    for (int i = t; i < ZPAIRS; i += stride) {
        float2 v = reinterpret_cast<const float2*>(Z)[i];
        __nv_bfloat162 b = __floats2bfloat162_rn(v.x, v.y);
        g_zbf[i] = *reinterpret_cast<uint32_t*>(&b);
    }
    for (int i = t; i < EPAIRS; i += stride) {
        float2 v = reinterpret_cast<const float2*>(E)[i];
        __nv_bfloat162 b = __floats2bfloat162_rn(v.x, v.y);
        g_ebf[i] = *reinterpret_cast<uint32_t*>(&b);
    }
}

__global__ void norms_kernel(const float* __restrict__ z, const float* __restrict__ e) {
    int gw = (blockIdx.x * blockDim.x + threadIdx.x) >> 5;
    int lane = threadIdx.x & 31;
    if (gw >= N_ROWS + K_CODES) return;
    const float* p = (gw < N_ROWS) ? (z + (size_t)gw * D_DIM)
                                   : (e + (size_t)(gw - N_ROWS) * D_DIM);
    float acc = 0.0f;
    #pragma unroll
    for (int i = lane; i < D_DIM; i += 32) { float v = p[i]; acc = fmaf(v, v, acc); }
    #pragma unroll
    for (int o = 16; o > 0; o >>= 1) acc += __shfl_down_sync(0xffffffffu, acc, o);
    if (lane == 0) { if (gw < N_ROWS) g_znorm[gw] = acc; else g_enorm[gw - N_ROWS] = acc; }
}

// ---------------------------------------------------------------------------
// bf16 m16n8k16 GEMM + running per-row best + margin candidate push.
// 8 warps as 2(m) x 4(n); warp tile 64x32; 3-stage cp.async pipeline.
// ---------------------------------------------------------------------------
__global__ __launch_bounds__(256, 2)
void vq_mma_kernel(const float* __restrict__, const float* __restrict__) {
    extern __shared__ uint32_t sm_u[];
    // layout: STAGES x [ Zs(128 x RSU u32) ; Es(128 x RSU u32) ], then rowbest
    int* s_rowbest = reinterpret_cast<int*>(sm_u + STAGES * 2 * BM * RSU);

    const int tid = threadIdx.x;
    const int wid = tid >> 5;
    const int l   = tid & 31;
    const int warp_m = wid >> 2;        // 0..1
    const int warp_n = wid & 3;         // 0..3
    const int l4 = l >> 2;              // 0..7
    const int kc = l & 3;               // 0..3
    const int row0 = blockIdx.x * BM;
    const int mrow = warp_m * 64 + l4;
    const int ncol = warp_n * 32 + l4;
    const int shard = blockIdx.x & (NSHARDS - 1);

    const uint32_t sm_base  = smem_u32(sm_u);
    const int      stage_u  = 2 * BM * RSU;                 // u32 per stage
    const uint32_t stage_b  = (uint32_t)stage_u * 4;
    const uint32_t eoff_b   = (uint32_t)(BM * RSU) * 4;

    if (tid < BM) s_rowbest[tid] = FLT_MAX_BITS;

    float zn[8];
    #pragma unroll
    for (int mi = 0; mi < 4; mi++)
        #pragma unroll
        for (int hi = 0; hi < 2; hi++)
            zn[mi * 2 + hi] = g_znorm[row0 + warp_m * 64 + mi * 16 + hi * 8 + l4];

    __syncthreads();

    const int DP = D_DIM / 2;   // row stride in pairs

    for (int c = 0; c < NCHUNKS; c++) {
        float acc[4][4][4];
        #pragma unroll
        for (int mi = 0; mi < 4; mi++)
            #pragma unroll
            for (int ni = 0; ni < 4; ni++)
                #pragma unroll
                for (int r = 0; r < 4; r++) acc[mi][ni][r] = 0.0f;

        const uint32_t* Zg0 = g_zbf + (size_t)row0 * DP;
        const uint32_t* Eg0 = g_ebf + (size_t)(c * BN) * DP;

        // prologue: k-iters 0,1 into stages 0,1
        #pragma unroll
        for (int pre = 0; pre < 2; pre++) {
            const int kp = pre * (BKE / 2);                 // pair offset
            const uint32_t zb = sm_base + (uint32_t)pre * stage_b;
            const uint32_t eb = zb + eoff_b;
            #pragma unroll
            for (int i = 0; i < 4; i++) {
                int u = tid + i * 256, r = u >> 3, s = u & 7;
                cpasync16(zb + r * (RSU * 4) + s * 16, Zg0 + (size_t)r * DP + kp + s * 4);
                cpasync16(eb + r * (RSU * 4) + s * 16, Eg0 + (size_t)r * DP + kp + s * 4);
            }
            CP_COMMIT();
        }

        for (int it = 0; it < KITERS; it++) {
            if (it == KITERS - 1) { CP_WAIT0(); } else { CP_WAITG1(); }
            __syncthreads();
            if (it + 2 < KITERS) {   // prefetch iter it+2 into stage (it+2)%3
                const int st = (it + 2) % STAGES;
                const int kp = (it + 2) * (BKE / 2);
                const uint32_t zb = sm_base + (uint32_t)st * stage_b;
                const uint32_t eb = zb + eoff_b;
                #pragma unroll
                for (int i = 0; i < 4; i++) {
                    int u = tid + i * 256, r = u >> 3, s = u & 7;
                    cpasync16(zb + r * (RSU * 4) + s * 16, Zg0 + (size_t)r * DP + kp + s * 4);
                    cpasync16(eb + r * (RSU * 4) + s * 16, Eg0 + (size_t)r * DP + kp + s * 4);
                }
                CP_COMMIT();
            }
            // compute on stage it%3: 4 ksteps of k16
            const uint32_t* Zt = sm_u + (it % STAGES) * stage_u;
            const uint32_t* Et = Zt + BM * RSU;
            #pragma unroll
            for (int ks = 0; ks < 4; ks++) {
                const int kp = ks * 8 + kc;                 // pair index within row
                uint32_t a[4][4], b[4][2];
                #pragma unroll
                for (int mi = 0; mi < 4; mi++) {
                    const int r = mrow + mi * 16;
                    a[mi][0] = Zt[r * RSU + kp];
                    a[mi][1] = Zt[(r + 8) * RSU + kp];
                    a[mi][2] = Zt[r * RSU + kp + 4];
                    a[mi][3] = Zt[(r + 8) * RSU + kp + 4];
                }
                #pragma unroll
                for (int ni = 0; ni < 4; ni++) {
                    const int n = ncol + ni * 8;
                    b[ni][0] = Et[n * RSU + kp];
                    b[ni][1] = Et[n * RSU + kp + 4];
                }
                #pragma unroll
                for (int mi = 0; mi < 4; mi++)
                    #pragma unroll
                    for (int ni = 0; ni < 4; ni++)
                        mma_bf16(acc[mi][ni], a[mi], b[ni]);
            }
        }

        // ---------- epilogue pass 1: per-row running min ----------
        const int colg0 = c * BN + warp_n * 32 + kc * 2;
        float dmin[8];
        #pragma unroll
        for (int i = 0; i < 8; i++) dmin[i] = 3.4028235e38f;
        #pragma unroll
        for (int ni = 0; ni < 4; ni++) {
            float en0 = __ldg(&g_enorm[colg0 + ni * 8]);
            float en1 = __ldg(&g_enorm[colg0 + ni * 8 + 1]);
            #pragma unroll
            for (int mi = 0; mi < 4; mi++) {
                float d0 = (zn[mi * 2] + en0)     - 2.0f * acc[mi][ni][0];
                float d1 = (zn[mi * 2] + en1)     - 2.0f * acc[mi][ni][1];
                float d2 = (zn[mi * 2 + 1] + en0) - 2.0f * acc[mi][ni][2];
                float d3 = (zn[mi * 2 + 1] + en1) - 2.0f * acc[mi][ni][3];
                dmin[mi * 2]     = fminf(dmin[mi * 2], fminf(d0, d1));
                dmin[mi * 2 + 1] = fminf(dmin[mi * 2 + 1], fminf(d2, d3));
            }
        }
        #pragma unroll
        for (int i = 0; i < 8; i++) {
            dmin[i] = fminf(dmin[i], __shfl_xor_sync(0xffffffffu, dmin[i], 1));
            dmin[i] = fminf(dmin[i], __shfl_xor_sync(0xffffffffu, dmin[i], 2));
        }
        if (kc == 0) {
            #pragma unroll
            for (int mi = 0; mi < 4; mi++) {
                atomicMin(&s_rowbest[warp_m * 64 + mi * 16 + l4],     __float_as_int(dmin[mi * 2]));
                atomicMin(&s_rowbest[warp_m * 64 + mi * 16 + 8 + l4], __float_as_int(dmin[mi * 2 + 1]));
            }
        }
        __syncthreads();

        // ---------- epilogue pass 2: margin candidate push ----------
        #pragma unroll
        for (int ni = 0; ni < 4; ni++) {
            float en0 = __ldg(&g_enorm[colg0 + ni * 8]);
            float en1 = __ldg(&g_enorm[colg0 + ni * 8 + 1]);
            #pragma unroll
            for (int mi = 0; mi < 4; mi++) {
                const int rl0 = warp_m * 64 + mi * 16 + l4;
                const int rl1 = rl0 + 8;
                const float b0 = __int_as_float(s_rowbest[rl0]) + MARGIN;
                const float b1 = __int_as_float(s_rowbest[rl1]) + MARGIN;
                float d0 = (zn[mi * 2] + en0)     - 2.0f * acc[mi][ni][0];
                float d1 = (zn[mi * 2] + en1)     - 2.0f * acc[mi][ni][1];
                float d2 = (zn[mi * 2 + 1] + en0) - 2.0f * acc[mi][ni][2];
                float d3 = (zn[mi * 2 + 1] + en1) - 2.0f * acc[mi][ni][3];
                if (d0 < b0) { int p = atomicAdd(&g_ncand[shard], 1);
                    if (p < SHARD_CAP) g_cand[shard][p] = ((row0 + rl0) << 13) | (colg0 + ni * 8); }
                if (d1 < b0) { int p = atomicAdd(&g_ncand[shard], 1);
                    if (p < SHARD_CAP) g_cand[shard][p] = ((row0 + rl0) << 13) | (colg0 + ni * 8 + 1); }
                if (d2 < b1) { int p = atomicAdd(&g_ncand[shard], 1);
                    if (p < SHARD_CAP) g_cand[shard][p] = ((row0 + rl1) << 13) | (colg0 + ni * 8); }
                if (d3 < b1) { int p = atomicAdd(&g_ncand[shard], 1);
                    if (p < SHARD_CAP) g_cand[shard][p] = ((row0 + rl1) << 13) | (colg0 + ni * 8 + 1); }
            }
        }
    }
}

// ---------------------------------------------------------------------------
// Exact fp32 refinement; coalesced float4 loads.
// ---------------------------------------------------------------------------
__global__ void refine_kernel(const float* __restrict__ Z, const float* __restrict__ E) {
    const int nwarps = (gridDim.x * blockDim.x) >> 5;
    const int gw     = (blockIdx.x * blockDim.x + threadIdx.x) >> 5;
    const int lane   = threadIdx.x & 31;

    for (int s = 0; s < NSHARDS; s++) {
        int n = g_ncand[s];
        if (n > SHARD_CAP) n = SHARD_CAP;
        for (int i = gw; i < n; i += nwarps) {
            int cd  = g_cand[s][i];
            int row = cd >> 13;
            int idx = cd & (K_CODES - 1);
            const float4* z4 = reinterpret_cast<const float4*>(Z + (size_t)row * D_DIM);
            const float4* e4 = reinterpret_cast<const float4*>(E + (size_t)idx * D_DIM);
            float4 zv[4], ev[4];
            #pragma unroll
            for (int j = 0; j < 4; j++) {
                zv[j] = z4[j * 32 + lane];
                ev[j] = e4[j * 32 + lane];
            }
            float dot = 0.0f;
            #pragma unroll
            for (int j = 0; j < 4; j++) {
                dot = fmaf(zv[j].x, ev[j].x, dot);
                dot = fmaf(zv[j].y, ev[j].y, dot);
                dot = fmaf(zv[j].z, ev[j].z, dot);
                dot = fmaf(zv[j].w, ev[j].w, dot);
            }
            #pragma unroll
            for (int o = 16; o > 0; o >>= 1) dot += __shfl_down_sync(0xffffffffu, dot, o);
            if (lane == 0) {
                float d = (g_znorm[row] + g_enorm[idx]) - 2.0f * dot;
                unsigned long long key = ((unsigned long long)__float_as_uint(d) << 32) | (unsigned)idx;
                atomicMin(&g_best[row], key);
            }
        }
    }
}

// ---------------------------------------------------------------------------
__global__ void gather_kernel(const float* __restrict__ Z, const float* __restrict__ E,
                              float* __restrict__ out, int out_size) {
    int row = blockIdx.x;
    int t   = threadIdx.x;   // 128
    int idx = (int)(g_best[row] & 0xFFFFFFFFull) & (K_CODES - 1);
    const float* e = E + (size_t)idx * D_DIM;
    const float* z = Z + (size_t)row * D_DIM;
    float* o = out + (size_t)row * D_DIM;

    double s = 0.0;
    #pragma unroll
    for (int i = 0; i < 4; i++) {
        int d = t + i * 128;
        float q  = e[d];
        float zc = z[d];
        float dq = q - zc;
        o[d] = zc + dq;
        s += (double)dq * (double)dq;
    }
    __shared__ double sh[128];
    sh[t] = s;
    __syncthreads();
    for (int o2 = 64; o2 > 0; o2 >>= 1) { if (t < o2) sh[t] += sh[t + o2]; __syncthreads(); }
    if (t == 0) {
        g_rowpart[row] = sh[0];
        if (out_size >= N_ROWS * D_DIM + 1 + N_ROWS)
            out[(size_t)N_ROWS * D_DIM + 1 + row] = (float)idx;
    }
}

__global__ void loss_kernel(float* __restrict__ out, int out_size) {
    __shared__ double sh[256];
    int t = threadIdx.x;
    double s = 0.0;
    for (int i = t; i < N_ROWS; i += 256) s += g_rowpart[i];
    sh[t] = s;
    __syncthreads();
    for (int o = 128; o > 0; o >>= 1) { if (t < o) sh[t] += sh[t + o]; __syncthreads(); }
    if (t == 0 && out_size >= N_ROWS * D_DIM + 1) {
        double m = sh[0] / ((double)N_ROWS * (double)D_DIM);
        out[(size_t)N_ROWS * D_DIM] = (float)(1.25 * m);
    }
}

// ---------------------------------------------------------------------------
extern "C" void kernel_launch(void* const* d_in, const int* in_sizes, int n_in,
                              void* d_out, int out_size) {
    const float* z = (const float*)d_in[0];
    const float* e = (const float*)d_in[1];
    if (n_in >= 2 && in_sizes[0] == K_CODES * D_DIM && in_sizes[1] == N_ROWS * D_DIM) {
        const float* tmp = z; z = e; e = tmp;
    }
    float* out = (float*)d_out;

    const int smem_bytes = STAGES * 2 * BM * RSU * 4 + BM * 4;   // 111104
    cudaFuncSetAttribute(vq_mma_kernel, cudaFuncAttributeMaxDynamicSharedMemorySize, smem_bytes);

    init_kernel<<<256, 256>>>();
    convert_kernel<<<1024, 256>>>(z, e);
    int norm_blocks = ((N_ROWS + K_CODES) * 32 + 255) / 256;
    norms_kernel<<<norm_blocks, 256>>>(z, e);
    vq_mma_kernel<<<N_ROWS / BM, 256, smem_bytes>>>(z, e);
    refine_kernel<<<1024, 256>>>(z, e);
    gather_kernel<<<N_ROWS, 128>>>(z, e, out, out_size);
    loss_kernel<<<1, 256>>>(out, out_size);
}

// round 6
// speedup vs baseline: 5.4293x; 1.0657x over previous
#include <cuda_runtime.h>
#include <cuda_bf16.h>
#include <cstdint>

#define N_ROWS 32768
#define K_CODES 8192
#define D_DIM 512

#define BM 128
#define BN 128
#define BKE 64              // bf16 k-elems per tile
#define STAGES 3
#define NCHUNKS 64          // K_CODES / BN
#define KITERS 8            // D_DIM / BKE
#define RSU 36              // row stride in uint32 (64/2 + 4 pad) = 144 B
#define MARGIN 1.2e-3f
#define NSHARDS 64
#define SHARD_CAP 65536
#define FLT_MAX_BITS 0x7f7fffff

#define ZPAIRS (N_ROWS * D_DIM / 2)
#define EPAIRS (K_CODES * D_DIM / 2)

// ---------------- scratch (static __device__, no allocs) ----------------
__device__ float  g_znorm[N_ROWS];
__device__ float  g_enorm[K_CODES];
__device__ uint32_t g_zbf[ZPAIRS];   // packed bf16x2
__device__ uint32_t g_ebf[EPAIRS];
__device__ unsigned long long g_best[N_ROWS];
__device__ int    g_cand[NSHARDS][SHARD_CAP];
__device__ int    g_ncand[NSHARDS];
__device__ double g_rowpart[N_ROWS];

// ---------------- helpers ----------------
__device__ __forceinline__ uint32_t smem_u32(const void* p) {
    uint32_t a;
    asm("{ .reg .u64 t; cvta.to.shared.u64 t, %1; cvt.u32.u64 %0, t; }" : "=r"(a) : "l"(p));
    return a;
}
__device__ __forceinline__ void cpasync16(uint32_t dst, const void* src) {
    asm volatile("cp.async.cg.shared.global [%0], [%1], 16;" :: "r"(dst), "l"(src));
}
#define CP_COMMIT() asm volatile("cp.async.commit_group;" ::: "memory")
#define CP_WAITG1() asm volatile("cp.async.wait_group 1;" ::: "memory")
#define CP_WAIT0()  asm volatile("cp.async.wait_group 0;" ::: "memory")

#define LDSM_X4(r0, r1, r2, r3, addr) \
    asm volatile("ldmatrix.sync.aligned.m8n8.x4.shared.b16 {%0,%1,%2,%3}, [%4];" \
        : "=r"(r0), "=r"(r1), "=r"(r2), "=r"(r3) : "r"(addr))

// m16n8k16 bf16 HMMA (sm_80 base feature)
__device__ __forceinline__ void mma_bf16(float* d, const uint32_t* a, const uint32_t* b) {
    asm volatile("mma.sync.aligned.m16n8k16.row.col.f32.bf16.bf16.f32 "
        "{%0,%1,%2,%3}, {%4,%5,%6,%7}, {%8,%9}, {%0,%1,%2,%3};"
        : "+f"(d[0]), "+f"(d[1]), "+f"(d[2]), "+f"(d[3])
        : "r"(a[0]), "r"(a[1]), "r"(a[2]), "r"(a[3]), "r"(b[0]), "r"(b[1]));
}

// ---------------------------------------------------------------------------
__global__ void init_kernel() {
    int t = blockIdx.x * blockDim.x + threadIdx.x;
    if (t < NSHARDS) g_ncand[t] = 0;
    for (int i = t; i < N_ROWS; i += gridDim.x * blockDim.x)
        g_best[i] = 0xFFFFFFFFFFFFFFFFULL;
}

__global__ void convert_kernel(const float* __restrict__ Z, const float* __restrict__ E) {
    const int stride = gridDim.x * blockDim.x;
    int t = blockIdx.x * blockDim.x + threadIdx.x;
    for (int i = t; i < ZPAIRS; i += stride) {
        float2 v = reinterpret_cast<const float2*>(Z)[i];
        __nv_bfloat162 b = __floats2bfloat162_rn(v.x, v.y);
        g_zbf[i] = *reinterpret_cast<uint32_t*>(&b);
    }
    for (int i = t; i < EPAIRS; i += stride) {
        float2 v = reinterpret_cast<const float2*>(E)[i];
        __nv_bfloat162 b = __floats2bfloat162_rn(v.x, v.y);
        g_ebf[i] = *reinterpret_cast<uint32_t*>(&b);
    }
}

__global__ void norms_kernel(const float* __restrict__ z, const float* __restrict__ e) {
    int gw = (blockIdx.x * blockDim.x + threadIdx.x) >> 5;
    int lane = threadIdx.x & 31;
    if (gw >= N_ROWS + K_CODES) return;
    const float* p = (gw < N_ROWS) ? (z + (size_t)gw * D_DIM)
                                   : (e + (size_t)(gw - N_ROWS) * D_DIM);
    float acc = 0.0f;
    #pragma unroll
    for (int i = lane; i < D_DIM; i += 32) { float v = p[i]; acc = fmaf(v, v, acc); }
    #pragma unroll
    for (int o = 16; o > 0; o >>= 1) acc += __shfl_down_sync(0xffffffffu, acc, o);
    if (lane == 0) { if (gw < N_ROWS) g_znorm[gw] = acc; else g_enorm[gw - N_ROWS] = acc; }
}

// ---------------------------------------------------------------------------
// bf16 m16n8k16 GEMM + running per-row best + margin candidate push.
// 8 warps as 2(m) x 4(n); warp tile 64x32; 3-stage cp.async pipeline;
// fragment loads via ldmatrix.x4 (6 per k16-step instead of 24 LDS.32).
// ---------------------------------------------------------------------------
__global__ __launch_bounds__(256, 2)
void vq_mma_kernel(const float* __restrict__, const float* __restrict__) {
    extern __shared__ uint32_t sm_u[];
    int* s_rowbest = reinterpret_cast<int*>(sm_u + STAGES * 2 * BM * RSU);

    const int tid = threadIdx.x;
    const int wid = tid >> 5;
    const int l   = tid & 31;
    const int warp_m = wid >> 2;        // 0..1
    const int warp_n = wid & 3;         // 0..3
    const int l4 = l >> 2;              // 0..7
    const int kc = l & 3;               // 0..3
    const int row0 = blockIdx.x * BM;
    const int shard = blockIdx.x & (NSHARDS - 1);

    const uint32_t sm_base  = smem_u32(sm_u);
    const int      stage_u  = 2 * BM * RSU;                 // u32 per stage
    const uint32_t stage_b  = (uint32_t)stage_u * 4;
    const uint32_t eoff_b   = (uint32_t)(BM * RSU) * 4;

    // ldmatrix per-lane byte offsets (within a stage)
    // A: lanes 0-15 -> rows, bit4 of lane -> k+8 elems (=16B)
    const uint32_t a_off = (uint32_t)((warp_m * 64 + (l & 15)) * RSU * 4 + ((l >> 4) * 16));
    // B: lanes 0-7: tile n+0..7,k0 | 8-15: same rows k+8 | 16-23: n+8 rows k0 | 24-31: n+8,k+8
    const uint32_t b_off = (uint32_t)((warp_n * 32 + (l & 7) + ((l >> 4) << 3)) * RSU * 4
                                      + (((l >> 3) & 1) * 16)) + eoff_b;

    if (tid < BM) s_rowbest[tid] = FLT_MAX_BITS;

    float zn[8];
    #pragma unroll
    for (int mi = 0; mi < 4; mi++)
        #pragma unroll
        for (int hi = 0; hi < 2; hi++)
            zn[mi * 2 + hi] = g_znorm[row0 + warp_m * 64 + mi * 16 + hi * 8 + l4];

    __syncthreads();

    const int DP = D_DIM / 2;   // global row stride in pairs

    for (int c = 0; c < NCHUNKS; c++) {
        float acc[4][4][4];
        #pragma unroll
        for (int mi = 0; mi < 4; mi++)
            #pragma unroll
            for (int ni = 0; ni < 4; ni++)
                #pragma unroll
                for (int r = 0; r < 4; r++) acc[mi][ni][r] = 0.0f;

        const uint32_t* Zg0 = g_zbf + (size_t)row0 * DP;
        const uint32_t* Eg0 = g_ebf + (size_t)(c * BN) * DP;

        #pragma unroll
        for (int pre = 0; pre < 2; pre++) {
            const int kp = pre * (BKE / 2);
            const uint32_t zb = sm_base + (uint32_t)pre * stage_b;
            const uint32_t eb = zb + eoff_b;
            #pragma unroll
            for (int i = 0; i < 4; i++) {
                int u = tid + i * 256, r = u >> 3, s = u & 7;
                cpasync16(zb + r * (RSU * 4) + s * 16, Zg0 + (size_t)r * DP + kp + s * 4);
                cpasync16(eb + r * (RSU * 4) + s * 16, Eg0 + (size_t)r * DP + kp + s * 4);
            }
            CP_COMMIT();
        }

        for (int it = 0; it < KITERS; it++) {
            if (it == KITERS - 1) { CP_WAIT0(); } else { CP_WAITG1(); }
            __syncthreads();
            if (it + 2 < KITERS) {
                const int st = (it + 2) % STAGES;
                const int kp = (it + 2) * (BKE / 2);
                const uint32_t zb = sm_base + (uint32_t)st * stage_b;
                const uint32_t eb = zb + eoff_b;
                #pragma unroll
                for (int i = 0; i < 4; i++) {
                    int u = tid + i * 256, r = u >> 3, s = u & 7;
                    cpasync16(zb + r * (RSU * 4) + s * 16, Zg0 + (size_t)r * DP + kp + s * 4);
                    cpasync16(eb + r * (RSU * 4) + s * 16, Eg0 + (size_t)r * DP + kp + s * 4);
                }
                CP_COMMIT();
            }
            const uint32_t stg = sm_base + (uint32_t)(it % STAGES) * stage_b;
            const uint32_t abase = stg + a_off;
            const uint32_t bbase = stg + b_off;
            #pragma unroll
            for (int ks = 0; ks < 4; ks++) {
                uint32_t a[4][4], b[4][2];
                #pragma unroll
                for (int mi = 0; mi < 4; mi++)
                    LDSM_X4(a[mi][0], a[mi][1], a[mi][2], a[mi][3],
                            abase + mi * (16 * RSU * 4) + ks * 32);
                #pragma unroll
                for (int np = 0; np < 2; np++)
                    LDSM_X4(b[2 * np][0], b[2 * np][1], b[2 * np + 1][0], b[2 * np + 1][1],
                            bbase + np * (16 * RSU * 4) + ks * 32);
                #pragma unroll
                for (int mi = 0; mi < 4; mi++)
                    #pragma unroll
                    for (int ni = 0; ni < 4; ni++)
                        mma_bf16(acc[mi][ni], a[mi], b[ni]);
            }
        }

        // ---------- epilogue pass 1: per-row running min ----------
        const int colg0 = c * BN + warp_n * 32 + kc * 2;
        float dmin[8];
        #pragma unroll
        for (int i = 0; i < 8; i++) dmin[i] = 3.4028235e38f;
        #pragma unroll
        for (int ni = 0; ni < 4; ni++) {
            float en0 = __ldg(&g_enorm[colg0 + ni * 8]);
            float en1 = __ldg(&g_enorm[colg0 + ni * 8 + 1]);
            #pragma unroll
            for (int mi = 0; mi < 4; mi++) {
                float d0 = (zn[mi * 2] + en0)     - 2.0f * acc[mi][ni][0];
                float d1 = (zn[mi * 2] + en1)     - 2.0f * acc[mi][ni][1];
                float d2 = (zn[mi * 2 + 1] + en0) - 2.0f * acc[mi][ni][2];
                float d3 = (zn[mi * 2 + 1] + en1) - 2.0f * acc[mi][ni][3];
                dmin[mi * 2]     = fminf(dmin[mi * 2], fminf(d0, d1));
                dmin[mi * 2 + 1] = fminf(dmin[mi * 2 + 1], fminf(d2, d3));
            }
        }
        #pragma unroll
        for (int i = 0; i < 8; i++) {
            dmin[i] = fminf(dmin[i], __shfl_xor_sync(0xffffffffu, dmin[i], 1));
            dmin[i] = fminf(dmin[i], __shfl_xor_sync(0xffffffffu, dmin[i], 2));
        }
        if (kc == 0) {
            #pragma unroll
            for (int mi = 0; mi < 4; mi++) {
                atomicMin(&s_rowbest[warp_m * 64 + mi * 16 + l4],     __float_as_int(dmin[mi * 2]));
                atomicMin(&s_rowbest[warp_m * 64 + mi * 16 + 8 + l4], __float_as_int(dmin[mi * 2 + 1]));
            }
        }
        __syncthreads();

        // ---------- epilogue pass 2: margin candidate push ----------
        #pragma unroll
        for (int ni = 0; ni < 4; ni++) {
            float en0 = __ldg(&g_enorm[colg0 + ni * 8]);
            float en1 = __ldg(&g_enorm[colg0 + ni * 8 + 1]);
            #pragma unroll
            for (int mi = 0; mi < 4; mi++) {
                const int rl0 = warp_m * 64 + mi * 16 + l4;
                const int rl1 = rl0 + 8;
                const float b0 = __int_as_float(s_rowbest[rl0]) + MARGIN;
                const float b1 = __int_as_float(s_rowbest[rl1]) + MARGIN;
                float d0 = (zn[mi * 2] + en0)     - 2.0f * acc[mi][ni][0];
                float d1 = (zn[mi * 2] + en1)     - 2.0f * acc[mi][ni][1];
                float d2 = (zn[mi * 2 + 1] + en0) - 2.0f * acc[mi][ni][2];
                float d3 = (zn[mi * 2 + 1] + en1) - 2.0f * acc[mi][ni][3];
                if (d0 < b0) { int p = atomicAdd(&g_ncand[shard], 1);
                    if (p < SHARD_CAP) g_cand[shard][p] = ((row0 + rl0) << 13) | (colg0 + ni * 8); }
                if (d1 < b0) { int p = atomicAdd(&g_ncand[shard], 1);
                    if (p < SHARD_CAP) g_cand[shard][p] = ((row0 + rl0) << 13) | (colg0 + ni * 8 + 1); }
                if (d2 < b1) { int p = atomicAdd(&g_ncand[shard], 1);
                    if (p < SHARD_CAP) g_cand[shard][p] = ((row0 + rl1) << 13) | (colg0 + ni * 8); }
                if (d3 < b1) { int p = atomicAdd(&g_ncand[shard], 1);
                    if (p < SHARD_CAP) g_cand[shard][p] = ((row0 + rl1) << 13) | (colg0 + ni * 8 + 1); }
            }
        }
    }
}

// ---------------------------------------------------------------------------
__global__ void refine_kernel(const float* __restrict__ Z, const float* __restrict__ E) {
    const int nwarps = (gridDim.x * blockDim.x) >> 5;
    const int gw     = (blockIdx.x * blockDim.x + threadIdx.x) >> 5;
    const int lane   = threadIdx.x & 31;

    for (int s = 0; s < NSHARDS; s++) {
        int n = g_ncand[s];
        if (n > SHARD_CAP) n = SHARD_CAP;
        for (int i = gw; i < n; i += nwarps) {
            int cd  = g_cand[s][i];
            int row = cd >> 13;
            int idx = cd & (K_CODES - 1);
            const float4* z4 = reinterpret_cast<const float4*>(Z + (size_t)row * D_DIM);
            const float4* e4 = reinterpret_cast<const float4*>(E + (size_t)idx * D_DIM);
            float4 zv[4], ev[4];
            #pragma unroll
            for (int j = 0; j < 4; j++) {
                zv[j] = z4[j * 32 + lane];
                ev[j] = e4[j * 32 + lane];
            }
            float dot = 0.0f;
            #pragma unroll
            for (int j = 0; j < 4; j++) {
                dot = fmaf(zv[j].x, ev[j].x, dot);
                dot = fmaf(zv[j].y, ev[j].y, dot);
                dot = fmaf(zv[j].z, ev[j].z, dot);
                dot = fmaf(zv[j].w, ev[j].w, dot);
            }
            #pragma unroll
            for (int o = 16; o > 0; o >>= 1) dot += __shfl_down_sync(0xffffffffu, dot, o);
            if (lane == 0) {
                float d = (g_znorm[row] + g_enorm[idx]) - 2.0f * dot;
                unsigned long long key = ((unsigned long long)__float_as_uint(d) << 32) | (unsigned)idx;
                atomicMin(&g_best[row], key);
            }
        }
    }
}

// ---------------------------------------------------------------------------
__global__ void gather_kernel(const float* __restrict__ Z, const float* __restrict__ E,
                              float* __restrict__ out, int out_size) {
    int row = blockIdx.x;
    int t   = threadIdx.x;   // 128
    int idx = (int)(g_best[row] & 0xFFFFFFFFull) & (K_CODES - 1);
    const float* e = E + (size_t)idx * D_DIM;
    const float* z = Z + (size_t)row * D_DIM;
    float* o = out + (size_t)row * D_DIM;

    double s = 0.0;
    #pragma unroll
    for (int i = 0; i < 4; i++) {
        int d = t + i * 128;
        float q  = e[d];
        float zc = z[d];
        float dq = q - zc;
        o[d] = zc + dq;
        s += (double)dq * (double)dq;
    }
    __shared__ double sh[128];
    sh[t] = s;
    __syncthreads();
    for (int o2 = 64; o2 > 0; o2 >>= 1) { if (t < o2) sh[t] += sh[t + o2]; __syncthreads(); }
    if (t == 0) {
        g_rowpart[row] = sh[0];
        if (out_size >= N_ROWS * D_DIM + 1 + N_ROWS)
            out[(size_t)N_ROWS * D_DIM + 1 + row] = (float)idx;
    }
}

__global__ void loss_kernel(float* __restrict__ out, int out_size) {
    __shared__ double sh[256];
    int t = threadIdx.x;
    double s = 0.0;
    for (int i = t; i < N_ROWS; i += 256) s += g_rowpart[i];
    sh[t] = s;
    __syncthreads();
    for (int o = 128; o > 0; o >>= 1) { if (t < o) sh[t] += sh[t + o]; __syncthreads(); }
    if (t == 0 && out_size >= N_ROWS * D_DIM + 1) {
        double m = sh[0] / ((double)N_ROWS * (double)D_DIM);
        out[(size_t)N_ROWS * D_DIM] = (float)(1.25 * m);
    }
}

// ---------------------------------------------------------------------------
extern "C" void kernel_launch(void* const* d_in, const int* in_sizes, int n_in,
                              void* d_out, int out_size) {
    const float* z = (const float*)d_in[0];
    const float* e = (const float*)d_in[1];
    if (n_in >= 2 && in_sizes[0] == K_CODES * D_DIM && in_sizes[1] == N_ROWS * D_DIM) {
        const float* tmp = z; z = e; e = tmp;
    }
    float* out = (float*)d_out;

    const int smem_bytes = STAGES * 2 * BM * RSU * 4 + BM * 4;   // 111104
    cudaFuncSetAttribute(vq_mma_kernel, cudaFuncAttributeMaxDynamicSharedMemorySize, smem_bytes);

    init_kernel<<<256, 256>>>();
    convert_kernel<<<1024, 256>>>(z, e);
    int norm_blocks = ((N_ROWS + K_CODES) * 32 + 255) / 256;
    norms_kernel<<<norm_blocks, 256>>>(z, e);
    vq_mma_kernel<<<N_ROWS / BM, 256, smem_bytes>>>(z, e);
    refine_kernel<<<1024, 256>>>(z, e);
    gather_kernel<<<N_ROWS, 128>>>(z, e, out, out_size);
    loss_kernel<<<1, 256>>>(out, out_size);
}